// round 8
// baseline (speedup 1.0000x reference)
#include <cuda_runtime.h>
#include <cuda_bf16.h>

// Problem constants (fixed shapes from setup_inputs)
#define B_DIM 8
#define T_DIM 4096
#define D_DIM 1024
#define K_FFT 64
#define F_DIM (K_FFT / 2 + 1)        // 33

#define NUM_CONV 128                 // B * D/64

// ---------------------------------------------------------------------------
// Conv-only kernel: per-(batch, 64-channel tile) filter build + register-
// resident circular convolution of the last K_FFT timesteps. The rest of the
// output is zeroed by a graph memset node issued before this kernel.
// ---------------------------------------------------------------------------
__global__ void __launch_bounds__(256, 4) spectral_conv_kernel(
    const float* __restrict__ x, const float* __restrict__ mask,
    const float* __restrict__ mix_w, float* __restrict__ out)
{
    __shared__ float g_sh[64 * F_DIM];        // sigmoid(mask) tile [dl][f]
    __shared__ float tab[K_FFT];              // cos(2*pi*n/64)
    __shared__ float w_sh[K_FFT * 64];        // window [k][dl]
    __shared__ float f_sh[64 * (K_FFT + 1)];  // filter [dl][n], pad 65

    const int bid = blockIdx.x;
    const int tid = threadIdx.x;

    const int b  = bid >> 4;          // 0..7
    const int d0 = (bid & 15) * 64;   // channel tile base

    // Stage sigmoid(mask) for the 64 channels (2112 contiguous floats).
    const float* mrow = mask + (long long)d0 * F_DIM;
    for (int idx = tid; idx < 64 * F_DIM; idx += 256)
        g_sh[idx] = 1.0f / (1.0f + expf(-mrow[idx]));
    if (tid < K_FFT)
        tab[tid] = cospif((float)tid * (1.0f / 32.0f));   // exact twiddles

    // Stage the last-64-timestep window (coalesced).
    const float* xb = x + ((long long)b * T_DIM + (T_DIM - K_FFT)) * D_DIM + d0;
    #pragma unroll
    for (int i = 0; i < 16; i++) {
        int idx = tid + i * 256;
        int k = idx >> 6, dl = idx & 63;
        w_sh[idx] = xb[(long long)k * D_DIM + dl];
    }
    __syncthreads();

    // f[dl][n] = mix_w/64 * ( g0 + 2*sum_{f=1..31} g_f cos(2 pi f n/64) + g32*(-1)^n )
    #pragma unroll
    for (int i = 0; i < 16; i++) {
        int idx = tid + i * 256;
        int dl = idx >> 6, n = idx & 63;
        const float* gd = g_sh + dl * F_DIM;
        float s = gd[0] + gd[32] * tab[(32 * n) & 63];
        #pragma unroll
        for (int f = 1; f < 32; f++)
            s += 2.0f * gd[f] * tab[(f * n) & 63];
        f_sh[dl * 65 + n] = s * (1.0f / 64.0f) * mix_w[d0 + dl];
    }
    __syncthreads();

    const int dl = tid & 63;
    const int t0 = (tid >> 6) * 16;

    // Pre-rotated filter in registers: fr[i] = f[(t0+i)&63]
    //   -> y[t0+j] = sum_k w[k] * fr[(j-k)&63], all compile-time reg indices.
    float fr[K_FFT];
    #pragma unroll
    for (int i = 0; i < K_FFT; i++)
        fr[i] = f_sh[dl * 65 + ((t0 + i) & 63)];

    float acc[16];
    #pragma unroll
    for (int j = 0; j < 16; j++) acc[j] = 0.0f;

    #pragma unroll
    for (int k = 0; k < K_FFT; k++) {
        float wv = w_sh[k * 64 + dl];
        #pragma unroll
        for (int j = 0; j < 16; j++)
            acc[j] += wv * fr[(j - k + K_FFT) & 63];
    }

    float* ob = out + ((long long)b * T_DIM + (T_DIM - K_FFT)) * D_DIM + d0;
    #pragma unroll
    for (int j = 0; j < 16; j++)
        ob[(long long)(t0 + j) * D_DIM + dl] = acc[j];
}

// ---------------------------------------------------------------------------
// Launch: memset node (driver fill path) + conv kernel node.
// cudaMemsetAsync on the capture stream becomes a graph memset node —
// no sync, no allocation. Conv overwrites the 2 MiB of window rows after.
// ---------------------------------------------------------------------------
extern "C" void kernel_launch(void* const* d_in, const int* in_sizes, int n_in,
                              void* d_out, int out_size)
{
    const float* x     = (const float*)d_in[0];   // (B, T, D) fp32
    const float* mask  = (const float*)d_in[1];   // (D, 33)   fp32
    const float* mix_w = (const float*)d_in[2];   // (D,)      fp32
    float* out = (float*)d_out;                   // (B, T, D) fp32

    // Zero the entire output via the driver's fill path.
    cudaMemsetAsync(out, 0, (size_t)out_size * sizeof(float), 0);

    // Compute the last-64-timestep windows (stream-ordered after the memset).
    spectral_conv_kernel<<<NUM_CONV, 256>>>(x, mask, mix_w, out);
}